// round 2
// baseline (speedup 1.0000x reference)
#include <cuda_runtime.h>
#include <cstdint>
#include <cstddef>

#define NUSERS   100000
#define NITEMS   50000
#define DIM      64
#define BATCH    1024
#define NCHAN    3

#define BT       32          // users per block tile
#define ITILE    64          // items per block tile
#define SV_STRIDE 132        // 128 dup floats + 4 pad (16B-aligned rows, conflict mitigation)
#define NTHREADS 128

// Scratch: weighted user rows, layout [j][d][b] (d-major, b contiguous)
__device__ float g_su[NCHAN * DIM * BATCH];

// ---------------------------------------------------------------------------
// Prep: su[j][d][b] = user_table[users[b]][d] * w_j[d]
// ---------------------------------------------------------------------------
__global__ void gmf_prep(const int* __restrict__ users,
                         const float* __restrict__ utab,
                         const float* __restrict__ wv,
                         const float* __restrict__ wc,
                         const float* __restrict__ wb)
{
    int d = blockIdx.x;                 // 0..63
    float w0 = wv[d], w1 = wc[d], w2 = wb[d];
    for (int b = threadIdx.x; b < BATCH; b += blockDim.x) {
        float u = utab[(size_t)users[b] * DIM + d];
        g_su[(0 * DIM + d) * BATCH + b] = u * w0;
        g_su[(1 * DIM + d) * BATCH + b] = u * w1;
        g_su[(2 * DIM + d) * BATCH + b] = u * w2;
    }
}

// ---------------------------------------------------------------------------
// Main: out[j][b][i] = sum_d su[j][d][b] * item_table[items[i]][d]
// Block tile: 32 users x 64 items, all 3 channels. K=64 in one smem load.
// Per-thread: 4 users x 4 items x 3 channels, users packed as f32x2 pairs.
// ---------------------------------------------------------------------------
__device__ __forceinline__ float lo32f(unsigned long long x) {
    return __uint_as_float((unsigned)x);
}
__device__ __forceinline__ float hi32f(unsigned long long x) {
    return __uint_as_float((unsigned)(x >> 32));
}

#define FFMA2(acc_, a_, b_) \
    asm("fma.rn.f32x2 %0, %1, %2, %0;" : "+l"(acc_) : "l"(a_), "l"(b_))

__global__ void __launch_bounds__(NTHREADS)
gmf_main(const float* __restrict__ itab,
         const int*   __restrict__ items,
         float*       __restrict__ out)
{
    extern __shared__ float smem[];
    float* ssu = smem;                      // [3][64][32]  (j*64+d)*32 + u
    float* sv  = smem + NCHAN * DIM * BT;   // [64][SV_STRIDE] dup: (v_i, v_i) at 2*i

    const int tid = threadIdx.x;
    const int tx  = tid & 15;               // item group (4 items)
    const int ty  = tid >> 4;               // user group (4 users)
    const int i0  = blockIdx.x * ITILE;
    const int b0  = blockIdx.y * BT;

    // --- fill su tile: rows of 32 contiguous floats, fully coalesced ---
    for (int idx = tid; idx < NCHAN * DIM * (BT / 4); idx += NTHREADS) {
        int q  = idx & 7;
        int dj = idx >> 3;                  // j*64 + d
        float4 f = *(const float4*)(g_su + (size_t)dj * BATCH + b0 + 4 * q);
        *(float4*)(ssu + dj * BT + 4 * q) = f;
    }

    // --- fill v tile, duplicated pairs (v,v), transposed to [d][2*item] ---
    for (int idx = tid; idx < ITILE * (DIM / 4); idx += NTHREADS) {
        int dq = idx & 15;                  // 4-d group within row
        int ii = idx >> 4;                  // item within tile
        int gi = i0 + ii; if (gi >= NITEMS) gi = NITEMS - 1;
        size_t row = (size_t)items[gi];
        float4 f = *(const float4*)(itab + row * DIM + 4 * dq);
        float* r = sv + (4 * dq) * SV_STRIDE + 2 * ii;
        *(float2*)(r)                 = make_float2(f.x, f.x);
        *(float2*)(r + SV_STRIDE)     = make_float2(f.y, f.y);
        *(float2*)(r + 2 * SV_STRIDE) = make_float2(f.z, f.z);
        *(float2*)(r + 3 * SV_STRIDE) = make_float2(f.w, f.w);
    }
    __syncthreads();

    // --- accumulate: acc[j][up][i] = f32x2 over user pair (4ty+2up, +1) ---
    unsigned long long acc[NCHAN][2][4];
#pragma unroll
    for (int j = 0; j < NCHAN; ++j)
#pragma unroll
        for (int up = 0; up < 2; ++up)
#pragma unroll
            for (int i = 0; i < 4; ++i) acc[j][up][i] = 0ull;

    const float* svp = sv + 8 * tx;         // dup pairs for items 4tx..4tx+3
    const float* sup = ssu + 4 * ty;        // users 4ty..4ty+3

#pragma unroll 8
    for (int d = 0; d < DIM; ++d) {
        ulonglong2 v01 = *(const ulonglong2*)(svp + d * SV_STRIDE);
        ulonglong2 v23 = *(const ulonglong2*)(svp + d * SV_STRIDE + 4);
        unsigned long long vv[4] = { v01.x, v01.y, v23.x, v23.y };
#pragma unroll
        for (int j = 0; j < NCHAN; ++j) {
            ulonglong2 u2 = *(const ulonglong2*)(sup + (j * DIM + d) * BT);
#pragma unroll
            for (int i = 0; i < 4; ++i) {
                FFMA2(acc[j][0][i], u2.x, vv[i]);
                FFMA2(acc[j][1][i], u2.y, vv[i]);
            }
        }
    }

    // --- epilogue: unpack pairs, vectorized float4 stores ---
    const int i = i0 + 4 * tx;
    if (i < NITEMS) {
#pragma unroll
        for (int j = 0; j < NCHAN; ++j) {
            size_t base = (size_t)j * BATCH * NITEMS;
#pragma unroll
            for (int up = 0; up < 2; ++up) {
                int b_lo = b0 + 4 * ty + 2 * up;
                float4 lo, hi;
                lo.x = lo32f(acc[j][up][0]); hi.x = hi32f(acc[j][up][0]);
                lo.y = lo32f(acc[j][up][1]); hi.y = hi32f(acc[j][up][1]);
                lo.z = lo32f(acc[j][up][2]); hi.z = hi32f(acc[j][up][2]);
                lo.w = lo32f(acc[j][up][3]); hi.w = hi32f(acc[j][up][3]);
                *(float4*)(out + base + (size_t)b_lo * NITEMS + i)       = lo;
                *(float4*)(out + base + (size_t)(b_lo + 1) * NITEMS + i) = hi;
            }
        }
    }
}

// ---------------------------------------------------------------------------
// Inputs (metadata order):
//  0 batch_users  int32  [1024]
//  1 whole_items  int32  [50000]
//  2 dropout      (unused, p=0 -> identity)
//  3 user_table   f32    [100000,64]
//  4 item_table   f32    [50000,64]
//  5 weight_view  f32    [64,1]
//  6 weight_cart  f32    [64,1]
//  7 weight_buy   f32    [64,1]
// Output: f32 [3][1024][50000] (view, cart, buy concatenated)
// ---------------------------------------------------------------------------
extern "C" void kernel_launch(void* const* d_in, const int* in_sizes, int n_in,
                              void* d_out, int out_size)
{
    const int*   users = (const int*)d_in[0];
    const int*   items = (const int*)d_in[1];
    const float* utab  = (const float*)d_in[3];
    const float* itab  = (const float*)d_in[4];
    const float* wv    = (const float*)d_in[5];
    const float* wc    = (const float*)d_in[6];
    const float* wb    = (const float*)d_in[7];
    float* out = (float*)d_out;

    gmf_prep<<<DIM, 256>>>(users, utab, wv, wc, wb);

    size_t smem = (size_t)(NCHAN * DIM * BT + DIM * SV_STRIDE) * sizeof(float); // 58368 B
    cudaFuncSetAttribute(gmf_main, cudaFuncAttributeMaxDynamicSharedMemorySize, (int)smem);

    dim3 grid((NITEMS + ITILE - 1) / ITILE, BATCH / BT);
    gmf_main<<<grid, NTHREADS, smem>>>(itab, items, out);
}

// round 5
// speedup vs baseline: 3.3823x; 3.3823x over previous
#include <cuda_runtime.h>
#include <cuda_bf16.h>
#include <cstdint>
#include <cstddef>

#define NITEMS   50000
#define DIM      64
#define BATCH    1024
#define NCHAN    3
#define MROWS    (NCHAN * BATCH)     // 3072
#define TM       128
#define TN       128
#define NT_N     391                 // ceil(50000/128)
#define NPAD     (NT_N * 128)        // 50048
#define MT_PER_CTA 8                 // 24 m-tiles / grid.y(3)
#define ROWB     144                 // smem row stride bytes (128 + 16 pad)

// ---------------- bf16-split scratch (device globals; no allocs) ------------
__device__ __nv_bfloat16 gA_hi[MROWS * DIM];
__device__ __nv_bfloat16 gA_lo[MROWS * DIM];
__device__ __nv_bfloat16 gB_hi[NPAD * DIM];
__device__ __nv_bfloat16 gB_lo[NPAD * DIM];

// ---------------- smem layout (bytes) ---------------------------------------
#define TILE_B   (128 * ROWB)        // 18432 per (hi or lo) tile
#define S_BH     0
#define S_BL     (S_BH + TILE_B)     // 18432
#define S_A0     (S_BL + TILE_B)     // 36864  (buf0: hi then lo)
#define S_A1     (S_A0 + 2 * TILE_B) // 73728  (buf1: hi then lo)
#define S_TOT    (S_A1 + 2 * TILE_B) // 110592

// ---------------- helpers ----------------------------------------------------
__device__ __forceinline__ uint32_t smem_u32(const void* p) {
    uint32_t a;
    asm("{ .reg .u64 t; cvta.to.shared.u64 t, %1; cvt.u32.u64 %0, t; }" : "=r"(a) : "l"(p));
    return a;
}

#define CP16(dst, src) \
    asm volatile("cp.async.cg.shared.global [%0], [%1], 16;" :: "r"(dst), "l"(src))

#define LDSM4(r, addr)                                                        \
    asm volatile("ldmatrix.sync.aligned.m8n8.x4.shared.b16 {%0,%1,%2,%3}, [%4];" \
        : "=r"((r)[0]), "=r"((r)[1]), "=r"((r)[2]), "=r"((r)[3]) : "r"(addr))

#define MMA(d, a, b0_, b1_)                                                   \
    asm volatile("mma.sync.aligned.m16n8k16.row.col.f32.bf16.bf16.f32 "       \
        "{%0,%1,%2,%3}, {%4,%5,%6,%7}, {%8,%9}, {%0,%1,%2,%3};"               \
        : "+f"((d)[0]), "+f"((d)[1]), "+f"((d)[2]), "+f"((d)[3])              \
        : "r"((a)[0]), "r"((a)[1]), "r"((a)[2]), "r"((a)[3]),                 \
          "r"(b0_), "r"(b1_))

// fill one 128-row tile pair (hi, lo) from global bf16 [128,64] into smem
__device__ __forceinline__ void fill_pair(uint32_t s_hi, uint32_t s_lo,
                                          const __nv_bfloat16* g_hi,
                                          const __nv_bfloat16* g_lo, int tid)
{
    // 128 rows x 8 chunks of 16B per tile
    for (int idx = tid; idx < 1024; idx += 256) {
        int row = idx >> 3, c = idx & 7;
        uint32_t off = row * ROWB + c * 16;
        const char* sh = (const char*)g_hi + row * 128 + c * 16;
        const char* sl = (const char*)g_lo + row * 128 + c * 16;
        CP16(s_hi + off, sh);
        CP16(s_lo + off, sl);
    }
}

// ---------------- prep kernels ----------------------------------------------
__global__ void gmf_prep_a(const int* __restrict__ users,
                           const float* __restrict__ utab,
                           const float* __restrict__ wv,
                           const float* __restrict__ wc,
                           const float* __restrict__ wb)
{
    int idx = blockIdx.x * 256 + threadIdx.x;
    if (idx >= MROWS * DIM) return;
    int d = idx & (DIM - 1);
    int row = idx >> 6;
    int j = row >> 10;
    int b = row & (BATCH - 1);
    const float* w = (j == 0) ? wv : ((j == 1) ? wc : wb);
    float a = utab[(size_t)users[b] * DIM + d] * w[d];
    __nv_bfloat16 hi = __float2bfloat16(a);
    gA_hi[idx] = hi;
    gA_lo[idx] = __float2bfloat16(a - __bfloat162float(hi));
}

__global__ void gmf_prep_b(const int* __restrict__ items,
                           const float* __restrict__ itab)
{
    int idx = blockIdx.x * 256 + threadIdx.x;
    if (idx >= NPAD * DIM) return;
    int d = idx & (DIM - 1);
    int i = idx >> 6;
    float v = 0.0f;
    if (i < NITEMS) v = itab[(size_t)items[i] * DIM + d];
    __nv_bfloat16 hi = __float2bfloat16(v);
    gB_hi[idx] = hi;
    gB_lo[idx] = __float2bfloat16(v - __bfloat162float(hi));
}

// ---------------- main GEMM --------------------------------------------------
// C[3072, 50048] = Ah*Bh^T + Ah*Bl^T + Al*Bh^T   (fp32 acc, K=64)
// grid (391, 3): each CTA owns one N tile of 128, loops 8 M tiles of 128.
__global__ void __launch_bounds__(256)
gmf_mma(float* __restrict__ out)
{
    extern __shared__ char smem[];
    const uint32_t sb = smem_u32(smem);
    const int tid  = threadIdx.x;
    const int wid  = tid >> 5, lane = tid & 31;
    const int wm   = wid & 3;          // m warp 0..3 (32 rows each)
    const int wn   = wid >> 2;         // n warp 0..1 (64 cols each)
    const int l16  = lane & 15;
    const int lh   = lane >> 4;
    const int n0   = blockIdx.x * TN;
    const int mbase = blockIdx.y * MT_PER_CTA;

    // prolog: B tile + A tile 0 (group 0)
    fill_pair(sb + S_BH, sb + S_BL,
              gB_hi + (size_t)n0 * DIM, gB_lo + (size_t)n0 * DIM, tid);
    fill_pair(sb + S_A0, sb + S_A0 + TILE_B,
              gA_hi + (size_t)(mbase * TM) * DIM,
              gA_lo + (size_t)(mbase * TM) * DIM, tid);
    asm volatile("cp.async.commit_group;" ::: "memory");

    // per-warp static smem offsets
    const uint32_t a_row_off = (32 * wm + l16) * ROWB + lh * 16;
    const uint32_t b_row_off = (64 * wn + l16) * ROWB + lh * 16;

    for (int it = 0; it < MT_PER_CTA; ++it) {
        if (it > 0) __syncthreads();   // prior compute done before buffer reuse
        if (it + 1 < MT_PER_CTA) {
            uint32_t nb = (it + 1) & 1 ? S_A1 : S_A0;
            size_t m1 = (size_t)((mbase + it + 1) * TM) * DIM;
            fill_pair(sb + nb, sb + nb + TILE_B, gA_hi + m1, gA_lo + m1, tid);
            asm volatile("cp.async.commit_group;" ::: "memory");
            asm volatile("cp.async.wait_group 1;" ::: "memory");
        } else {
            asm volatile("cp.async.wait_group 0;" ::: "memory");
        }
        __syncthreads();

        const uint32_t Ah = sb + ((it & 1) ? S_A1 : S_A0);
        const uint32_t Al = Ah + TILE_B;
        const uint32_t Bh = sb + S_BH;
        const uint32_t Bl = sb + S_BL;

        float acc[2][8][4];
#pragma unroll
        for (int mt = 0; mt < 2; ++mt)
#pragma unroll
            for (int nt = 0; nt < 8; ++nt)
#pragma unroll
                for (int q = 0; q < 4; ++q) acc[mt][nt][q] = 0.0f;

#pragma unroll
        for (int c = 0; c < 4; ++c) {
            const uint32_t koff = c * 32;
            uint32_t ah[2][4], al[2][4], bh[8][2], bl[8][2];
#pragma unroll
            for (int mt = 0; mt < 2; ++mt) {
                uint32_t ao = a_row_off + mt * (16 * ROWB) + koff;
                LDSM4(ah[mt], Ah + ao);
                LDSM4(al[mt], Al + ao);
            }
#pragma unroll
            for (int g = 0; g < 4; ++g) {
                uint32_t bo = b_row_off + g * (16 * ROWB) + koff;
                uint32_t r[4];
                LDSM4(r, Bh + bo);
                bh[2 * g][0] = r[0]; bh[2 * g][1] = r[2];
                bh[2 * g + 1][0] = r[1]; bh[2 * g + 1][1] = r[3];
                LDSM4(r, Bl + bo);
                bl[2 * g][0] = r[0]; bl[2 * g][1] = r[2];
                bl[2 * g + 1][0] = r[1]; bl[2 * g + 1][1] = r[3];
            }
#pragma unroll
            for (int mt = 0; mt < 2; ++mt)
#pragma unroll
                for (int nt = 0; nt < 8; ++nt) {
                    MMA(acc[mt][nt], ah[mt], bh[nt][0], bh[nt][1]);
                    MMA(acc[mt][nt], ah[mt], bl[nt][0], bl[nt][1]);
                    MMA(acc[mt][nt], al[mt], bh[nt][0], bh[nt][1]);
                }
        }

        // epilogue: fragment stores (32B-sector aligned float2 pairs)
        const int m0 = (mbase + it) * TM;
        const int r0 = m0 + 32 * wm + (lane >> 2);
        const int cb = n0 + 64 * wn + 2 * (lane & 3);
#pragma unroll
        for (int mt = 0; mt < 2; ++mt) {
#pragma unroll
            for (int nt = 0; nt < 8; ++nt) {
                int col = cb + 8 * nt;
                if (col < NITEMS) {
                    int row = r0 + 16 * mt;
                    float2 v0 = make_float2(acc[mt][nt][0], acc[mt][nt][1]);
                    float2 v1 = make_float2(acc[mt][nt][2], acc[mt][nt][3]);
                    *(float2*)(out + (size_t)row * NITEMS + col) = v0;
                    *(float2*)(out + (size_t)(row + 8) * NITEMS + col) = v1;
                }
            }
        }
    }
}

// ---------------------------------------------------------------------------
// Inputs: 0 users i32[1024], 1 items i32[50000], 2 dropout (unused),
//         3 user_table f32[100000,64], 4 item_table f32[50000,64],
//         5 wv f32[64,1], 6 wc f32[64,1], 7 wb f32[64,1]
// Output: f32 [3][1024][50000]
// ---------------------------------------------------------------------------
extern "C" void kernel_launch(void* const* d_in, const int* in_sizes, int n_in,
                              void* d_out, int out_size)
{
    const int*   users = (const int*)d_in[0];
    const int*   items = (const int*)d_in[1];
    const float* utab  = (const float*)d_in[3];
    const float* itab  = (const float*)d_in[4];
    const float* wv    = (const float*)d_in[5];
    const float* wc    = (const float*)d_in[6];
    const float* wb    = (const float*)d_in[7];
    float* out = (float*)d_out;

    gmf_prep_a<<<(MROWS * DIM + 255) / 256, 256>>>(users, utab, wv, wc, wb);
    gmf_prep_b<<<(NPAD * DIM + 255) / 256, 256>>>(items, itab);

    cudaFuncSetAttribute(gmf_mma, cudaFuncAttributeMaxDynamicSharedMemorySize, S_TOT);
    dim3 grid(NT_N, 3);
    gmf_mma<<<grid, 256, S_TOT>>>(out);
}

// round 10
// speedup vs baseline: 4.1650x; 1.2314x over previous
#include <cuda_runtime.h>
#include <cuda_fp16.h>
#include <cstdint>
#include <cstddef>

#define NITEMS   50000
#define DIM      64
#define BATCH    1024
#define NCHAN    3
#define MROWS    (NCHAN * BATCH)     // 3072
#define TM       128
#define TN       128
#define NT_N     391                 // ceil(50000/128)
#define NPAD     (NT_N * 128)        // 50048
#define MT_PER_CTA 8                 // 24 m-tiles / grid.y(3)
#define ROWB     144                 // smem row stride bytes (128 + 16 pad)

#define A_SCALE  512.0f
#define B_SCALE  512.0f
#define OUT_SCALE (1.0f / (A_SCALE * B_SCALE))   // exact 2^-18

// ---------------- fp16 scratch (device globals; no allocs) ------------------
__device__ __half gA[MROWS * DIM];       // round(A * 2^9)   (A = u*w)
__device__ __half gB_hi[NPAD * DIM];     // round(B * 2^9)
__device__ __half gB_lo[NPAD * DIM];     // residual of B * 2^9

// ---------------- smem layout (bytes) ---------------------------------------
#define TILE_B   (128 * ROWB)        // 18432 per tile
#define S_BH     0
#define S_BL     (S_BH + TILE_B)     // 18432
#define S_A0     (S_BL + TILE_B)     // 36864
#define S_A1     (S_A0 + TILE_B)     // 55296
#define S_TOT    (S_A1 + TILE_B)     // 73728  -> 2 CTAs/SM

// ---------------- helpers ----------------------------------------------------
__device__ __forceinline__ uint32_t smem_u32(const void* p) {
    uint32_t a;
    asm("{ .reg .u64 t; cvta.to.shared.u64 t, %1; cvt.u32.u64 %0, t; }" : "=r"(a) : "l"(p));
    return a;
}

#define CP16(dst, src) \
    asm volatile("cp.async.cg.shared.global [%0], [%1], 16;" :: "r"(dst), "l"(src))

#define LDSM4(r, addr)                                                        \
    asm volatile("ldmatrix.sync.aligned.m8n8.x4.shared.b16 {%0,%1,%2,%3}, [%4];" \
        : "=r"((r)[0]), "=r"((r)[1]), "=r"((r)[2]), "=r"((r)[3]) : "r"(addr))

#define MMA(d, a, b0_, b1_)                                                   \
    asm volatile("mma.sync.aligned.m16n8k16.row.col.f32.f16.f16.f32 "         \
        "{%0,%1,%2,%3}, {%4,%5,%6,%7}, {%8,%9}, {%0,%1,%2,%3};"               \
        : "+f"((d)[0]), "+f"((d)[1]), "+f"((d)[2]), "+f"((d)[3])              \
        : "r"((a)[0]), "r"((a)[1]), "r"((a)[2]), "r"((a)[3]),                 \
          "r"(b0_), "r"(b1_))

// fill one 128x64 fp16 tile (128B rows) into padded smem via cp.async
__device__ __forceinline__ void fill_one(uint32_t s, const __half* g, int tid)
{
    for (int idx = tid; idx < 1024; idx += 256) {
        int row = idx >> 3, c = idx & 7;
        CP16(s + row * ROWB + c * 16, (const char*)g + row * 128 + c * 16);
    }
}

// ---------------- prep: A rounded, B split hi/lo, all scaled by 2^9 ---------
__global__ void gmf_prep(const int* __restrict__ users,
                         const int* __restrict__ items,
                         const float* __restrict__ utab,
                         const float* __restrict__ itab,
                         const float* __restrict__ wv,
                         const float* __restrict__ wc,
                         const float* __restrict__ wb)
{
    int idx = blockIdx.x * 256 + threadIdx.x;
    if (idx < NPAD * DIM) {
        int d = idx & (DIM - 1);
        int i = idx >> 6;
        float v = 0.0f;
        if (i < NITEMS) v = itab[(size_t)items[i] * DIM + d] * B_SCALE;
        __half hi = __float2half_rn(v);
        gB_hi[idx] = hi;
        gB_lo[idx] = __float2half_rn(v - __half2float(hi));
    }
    if (idx < MROWS * DIM) {
        int d = idx & (DIM - 1);
        int row = idx >> 6;
        int j = row >> 10;
        int b = row & (BATCH - 1);
        const float* w = (j == 0) ? wv : ((j == 1) ? wc : wb);
        float a = utab[(size_t)users[b] * DIM + d] * w[d] * A_SCALE;
        gA[idx] = __float2half_rn(a);
    }
}

// ---------------- main GEMM --------------------------------------------------
// C = Ah*Bh^T + Ah*Bl^T  (fp32 acc, K=64); out = C * 2^-18
// grid (391, 3): each CTA owns one N tile of 128, loops 8 M tiles of 128.
__global__ void __launch_bounds__(256, 2)
gmf_mma(float* __restrict__ out)
{
    extern __shared__ char smem[];
    const uint32_t sb = smem_u32(smem);
    const int tid  = threadIdx.x;
    const int wid  = tid >> 5, lane = tid & 31;
    const int wm   = wid & 3;          // m warp 0..3 (32 rows each)
    const int wn   = wid >> 2;         // n warp 0..1 (64 cols each)
    const int l16  = lane & 15;
    const int lh   = lane >> 4;
    const int n0   = blockIdx.x * TN;
    const int mbase = blockIdx.y * MT_PER_CTA;

    // prolog: B tiles + A tile 0 in group 0
    fill_one(sb + S_BH, gB_hi + (size_t)n0 * DIM, tid);
    fill_one(sb + S_BL, gB_lo + (size_t)n0 * DIM, tid);
    fill_one(sb + S_A0, gA + (size_t)(mbase * TM) * DIM, tid);
    asm volatile("cp.async.commit_group;" ::: "memory");

    const uint32_t a_row_off = (32 * wm + l16) * ROWB + lh * 16;
    const uint32_t b_row_off = (64 * wn + l16) * ROWB + lh * 16;

    for (int it = 0; it < MT_PER_CTA; ++it) {
        if (it > 0) __syncthreads();   // prior compute done before buffer reuse
        if (it + 1 < MT_PER_CTA) {
            uint32_t nb = (it + 1) & 1 ? S_A1 : S_A0;
            fill_one(sb + nb, gA + (size_t)((mbase + it + 1) * TM) * DIM, tid);
            asm volatile("cp.async.commit_group;" ::: "memory");
            asm volatile("cp.async.wait_group 1;" ::: "memory");
        } else {
            asm volatile("cp.async.wait_group 0;" ::: "memory");
        }
        __syncthreads();

        const uint32_t Ah = sb + ((it & 1) ? S_A1 : S_A0);
        const uint32_t Bh = sb + S_BH;
        const uint32_t Bl = sb + S_BL;

        float acc[2][8][4];
#pragma unroll
        for (int mt = 0; mt < 2; ++mt)
#pragma unroll
            for (int nt = 0; nt < 8; ++nt)
#pragma unroll
                for (int q = 0; q < 4; ++q) acc[mt][nt][q] = 0.0f;

#pragma unroll
        for (int c = 0; c < 4; ++c) {
            const uint32_t koff = c * 32;
            uint32_t ah[2][4], bh[8][2], bl[8][2];
#pragma unroll
            for (int mt = 0; mt < 2; ++mt)
                LDSM4(ah[mt], Ah + a_row_off + mt * (16 * ROWB) + koff);
#pragma unroll
            for (int g = 0; g < 4; ++g) {
                uint32_t bo = b_row_off + g * (16 * ROWB) + koff;
                uint32_t r[4];
                LDSM4(r, Bh + bo);
                bh[2 * g][0] = r[0]; bh[2 * g][1] = r[2];
                bh[2 * g + 1][0] = r[1]; bh[2 * g + 1][1] = r[3];
                LDSM4(r, Bl + bo);
                bl[2 * g][0] = r[0]; bl[2 * g][1] = r[2];
                bl[2 * g + 1][0] = r[1]; bl[2 * g + 1][1] = r[3];
            }
#pragma unroll
            for (int mt = 0; mt < 2; ++mt)
#pragma unroll
                for (int nt = 0; nt < 8; ++nt) {
                    MMA(acc[mt][nt], ah[mt], bh[nt][0], bh[nt][1]);
                    MMA(acc[mt][nt], ah[mt], bl[nt][0], bl[nt][1]);
                }
        }

        // epilogue: rescale by exact 2^-18, float2 stores
        const int m0 = (mbase + it) * TM;
        const int r0 = m0 + 32 * wm + (lane >> 2);
        const int cb = n0 + 64 * wn + 2 * (lane & 3);
#pragma unroll
        for (int mt = 0; mt < 2; ++mt) {
#pragma unroll
            for (int nt = 0; nt < 8; ++nt) {
                int col = cb + 8 * nt;
                if (col < NITEMS) {
                    int row = r0 + 16 * mt;
                    float2 v0 = make_float2(acc[mt][nt][0] * OUT_SCALE,
                                            acc[mt][nt][1] * OUT_SCALE);
                    float2 v1 = make_float2(acc[mt][nt][2] * OUT_SCALE,
                                            acc[mt][nt][3] * OUT_SCALE);
                    *(float2*)(out + (size_t)row * NITEMS + col) = v0;
                    *(float2*)(out + (size_t)(row + 8) * NITEMS + col) = v1;
                }
            }
        }
    }
}

// ---------------------------------------------------------------------------
// Inputs: 0 users i32[1024], 1 items i32[50000], 2 dropout (unused),
//         3 user_table f32[100000,64], 4 item_table f32[50000,64],
//         5 wv f32[64,1], 6 wc f32[64,1], 7 wb f32[64,1]
// Output: f32 [3][1024][50000]
// ---------------------------------------------------------------------------
extern "C" void kernel_launch(void* const* d_in, const int* in_sizes, int n_in,
                              void* d_out, int out_size)
{
    const int*   users = (const int*)d_in[0];
    const int*   items = (const int*)d_in[1];
    const float* utab  = (const float*)d_in[3];
    const float* itab  = (const float*)d_in[4];
    const float* wv    = (const float*)d_in[5];
    const float* wc    = (const float*)d_in[6];
    const float* wb    = (const float*)d_in[7];
    float* out = (float*)d_out;

    gmf_prep<<<(NPAD * DIM + 255) / 256, 256>>>(users, items, utab, itab, wv, wc, wb);

    cudaFuncSetAttribute(gmf_mma, cudaFuncAttributeMaxDynamicSharedMemorySize, S_TOT);
    dim3 grid(NT_N, 3);
    gmf_mma<<<grid, 256, S_TOT>>>(out);
}